// round 3
// baseline (speedup 1.0000x reference)
#include <cuda_runtime.h>
#include <math.h>

#define Bb 8
#define HH 64
#define WWw 64
#define CC 512
#define GG 32
#define CGc (CC/GG)          /* 16 */
#define NTOK (HH*WWw)        /* 4096 */
#define EPSV 1e-5f

// ---------------- scratch (device globals; no runtime allocation) ----------------
__device__ float g_h [(size_t)Bb*NTOK*CC];
__device__ float g_q [(size_t)Bb*NTOK*CC];
__device__ float g_k [(size_t)Bb*NTOK*CC];
__device__ float g_v [(size_t)Bb*NTOK*CC];
__device__ float g_ao[(size_t)Bb*NTOK*CC];
__device__ float g_s [(size_t)Bb*NTOK*NTOK];   // 512 MB scores

// ---------------- GroupNorm ----------------
// one block per (batch, group); reduce over NTOK*CGc = 65536 elems
__global__ void gn_kernel(const float* __restrict__ x,
                          const float* __restrict__ sc,
                          const float* __restrict__ bi,
                          float* __restrict__ h) {
    int b = blockIdx.x / GG, g = blockIdx.x % GG;
    const float* xp = x + (size_t)b*NTOK*CC + g*CGc;
    float*       hp = h + (size_t)b*NTOK*CC + g*CGc;
    int tid = threadIdx.x;

    float s = 0.f, ss = 0.f;
    for (int i = tid; i < NTOK*CGc; i += 256) {
        int n = i >> 4, c = i & 15;
        float v = xp[(size_t)n*CC + c];
        s += v; ss += v*v;
    }
    __shared__ float r1[256], r2[256];
    r1[tid] = s; r2[tid] = ss; __syncthreads();
    for (int o = 128; o > 0; o >>= 1) {
        if (tid < o) { r1[tid] += r1[tid+o]; r2[tid] += r2[tid+o]; }
        __syncthreads();
    }
    const float invn = 1.f / (float)(NTOK*CGc);
    float mean = r1[0] * invn;
    float var  = r2[0] * invn - mean*mean;
    float inv  = rsqrtf(var + EPSV);

    for (int i = tid; i < NTOK*CGc; i += 256) {
        int n = i >> 4, c = i & 15;
        float v = xp[(size_t)n*CC + c];
        hp[(size_t)n*CC + c] = (v - mean) * inv * sc[g*CGc + c] + bi[g*CGc + c];
    }
}

// ---------------- tiled fp32 GEMM ----------------
// C[M,N] = alpha * A[M,K] @ op(B) + bias + resid
// TRANSB=false: B is [K,N] row-major.  TRANSB=true: B is [N,K] row-major (S = Q K^T).
#define BM 128
#define BN 128
#define BKK 16

template<bool TRANSB>
__global__ __launch_bounds__(256, 2)
void gemm_kernel(const float* __restrict__ A, int lda, long long sA,
                 const float* __restrict__ Bm, int ldb, long long sB,
                 float* __restrict__ Cm, int ldc, long long sC,
                 const float* __restrict__ bias,
                 const float* __restrict__ resid,
                 float alpha, int M, int Nc, int K) {
    __shared__ float As[BKK][BM+4];
    __shared__ float Bs[BKK][BN+4];

    const float* Ab = A  + (size_t)blockIdx.z * sA;
    const float* Bp = Bm + (size_t)blockIdx.z * sB;
    float*       Cb = Cm + (size_t)blockIdx.z * sC;
    const float* Rb = resid;   // only used when gridDim.z==1

    int m0 = blockIdx.y * BM, n0 = blockIdx.x * BN;
    int tid = threadIdx.x;
    int tx = tid & 15, ty = tid >> 4;

    float acc[8][8];
    #pragma unroll
    for (int i = 0; i < 8; i++)
        #pragma unroll
        for (int j = 0; j < 8; j++) acc[i][j] = 0.f;

    for (int k0 = 0; k0 < K; k0 += BKK) {
        // load A tile 128x16 (K contiguous per lane -> coalesced)
        #pragma unroll
        for (int t = 0; t < 2; t++) {
            int l  = tid + t*256;
            int m  = l >> 2;
            int kq = (l & 3) << 2;
            float4 v = *(const float4*)(Ab + (size_t)(m0+m)*lda + (k0+kq));
            As[kq+0][m] = v.x; As[kq+1][m] = v.y; As[kq+2][m] = v.z; As[kq+3][m] = v.w;
        }
        if (TRANSB) {
            #pragma unroll
            for (int t = 0; t < 2; t++) {
                int l  = tid + t*256;
                int n  = l >> 2;
                int kq = (l & 3) << 2;
                float4 v = *(const float4*)(Bp + (size_t)(n0+n)*ldb + (k0+kq));
                Bs[kq+0][n] = v.x; Bs[kq+1][n] = v.y; Bs[kq+2][n] = v.z; Bs[kq+3][n] = v.w;
            }
        } else {
            #pragma unroll
            for (int t = 0; t < 2; t++) {
                int l  = tid + t*256;
                int k  = l >> 5;
                int nq = (l & 31) << 2;
                *(float4*)&Bs[k][nq] = *(const float4*)(Bp + (size_t)(k0+k)*ldb + n0 + nq);
            }
        }
        __syncthreads();

        #pragma unroll
        for (int kk = 0; kk < BKK; kk++) {
            float a[8], b[8];
            *(float4*)&a[0] = *(const float4*)&As[kk][ty*4];
            *(float4*)&a[4] = *(const float4*)&As[kk][ty*4 + 64];
            *(float4*)&b[0] = *(const float4*)&Bs[kk][tx*4];
            *(float4*)&b[4] = *(const float4*)&Bs[kk][tx*4 + 64];
            #pragma unroll
            for (int i = 0; i < 8; i++)
                #pragma unroll
                for (int j = 0; j < 8; j++)
                    acc[i][j] = fmaf(a[i], b[j], acc[i][j]);
        }
        __syncthreads();
    }

    // epilogue: row(i) = m0 + ty*4 + (i%4) + (i/4)*64 ; col(j) analogous with tx
    #pragma unroll
    for (int i = 0; i < 8; i++) {
        int m = m0 + (ty<<2) + (i & 3) + ((i >> 2) << 6);
        size_t crow = (size_t)m * ldc;
        #pragma unroll
        for (int jh = 0; jh < 2; jh++) {
            int n = n0 + (tx<<2) + (jh << 6);
            float4 o;
            o.x = acc[i][jh*4+0] * alpha;
            o.y = acc[i][jh*4+1] * alpha;
            o.z = acc[i][jh*4+2] * alpha;
            o.w = acc[i][jh*4+3] * alpha;
            if (bias) {
                o.x += bias[n];   o.y += bias[n+1];
                o.z += bias[n+2]; o.w += bias[n+3];
            }
            if (Rb) {
                float4 r = *(const float4*)(Rb + crow + n);
                o.x += r.x; o.y += r.y; o.z += r.z; o.w += r.w;
            }
            *(float4*)(Cb + crow + n) = o;
        }
    }
}

// ---------------- row softmax (one block per row, values cached in regs) ----------------
__global__ void softmax_kernel(float* __restrict__ s) {
    size_t row = blockIdx.x;
    float* p = s + row * (size_t)NTOK;
    int tid = threadIdx.x;

    float vals[16];
    float m = -3.4e38f;
    #pragma unroll
    for (int t = 0; t < 16; t++) {
        vals[t] = p[tid + t*256];
        m = fmaxf(m, vals[t]);
    }
    __shared__ float red[256];
    red[tid] = m; __syncthreads();
    for (int o = 128; o > 0; o >>= 1) {
        if (tid < o) red[tid] = fmaxf(red[tid], red[tid+o]);
        __syncthreads();
    }
    m = red[0]; __syncthreads();

    float sum = 0.f;
    #pragma unroll
    for (int t = 0; t < 16; t++) {
        vals[t] = __expf(vals[t] - m);
        sum += vals[t];
    }
    red[tid] = sum; __syncthreads();
    for (int o = 128; o > 0; o >>= 1) {
        if (tid < o) red[tid] += red[tid+o];
        __syncthreads();
    }
    float r = 1.f / red[0];
    #pragma unroll
    for (int t = 0; t < 16; t++) p[tid + t*256] = vals[t] * r;
}

// ---------------- launch ----------------
extern "C" void kernel_launch(void* const* d_in, const int* in_sizes, int n_in,
                              void* d_out, int out_size) {
    const float* x  = (const float*)d_in[0];
    const float* gs = (const float*)d_in[1];
    const float* gb = (const float*)d_in[2];
    const float* wq = (const float*)d_in[3];
    const float* bq = (const float*)d_in[4];
    const float* wk = (const float*)d_in[5];
    const float* bk = (const float*)d_in[6];
    const float* wv = (const float*)d_in[7];
    const float* bv = (const float*)d_in[8];
    const float* wo = (const float*)d_in[9];
    const float* bo = (const float*)d_in[10];
    float* out = (float*)d_out;

    float *h, *q, *k, *v, *ao, *s;
    cudaGetSymbolAddress((void**)&h,  g_h);
    cudaGetSymbolAddress((void**)&q,  g_q);
    cudaGetSymbolAddress((void**)&k,  g_k);
    cudaGetSymbolAddress((void**)&v,  g_v);
    cudaGetSymbolAddress((void**)&ao, g_ao);
    cudaGetSymbolAddress((void**)&s,  g_s);

    const long long sNC = (long long)NTOK * CC;   // per-batch q/k/v stride
    const long long sNN = (long long)NTOK * NTOK; // per-batch scores stride
    const int Mtot = Bb * NTOK;                   // 32768
    const float inv_sqrt_c = 0.044194173824159216f; // 512^-0.5

    // 1) GroupNorm
    gn_kernel<<<Bb*GG, 256>>>(x, gs, gb, h);

    // 2) Q, K, V projections: [32768,512] @ [512,512] + bias
    dim3 gproj(CC/BN, Mtot/BM, 1);
    gemm_kernel<false><<<gproj, 256>>>(h, CC, 0, wq, CC, 0, q, CC, 0, bq, nullptr, 1.f, Mtot, CC, CC);
    gemm_kernel<false><<<gproj, 256>>>(h, CC, 0, wk, CC, 0, k, CC, 0, bk, nullptr, 1.f, Mtot, CC, CC);
    gemm_kernel<false><<<gproj, 256>>>(h, CC, 0, wv, CC, 0, v, CC, 0, bv, nullptr, 1.f, Mtot, CC, CC);

    // 3) scores = alpha * Q @ K^T  (batched over z)
    dim3 gsc(NTOK/BN, NTOK/BM, Bb);
    gemm_kernel<true><<<gsc, 256>>>(q, CC, sNC, k, CC, sNC, s, NTOK, sNN,
                                    nullptr, nullptr, inv_sqrt_c, NTOK, NTOK, CC);

    // 4) softmax over keys
    softmax_kernel<<<Bb*NTOK, 256>>>(s);

    // 5) attn @ V  (batched)
    dim3 gav(CC/BN, NTOK/BM, Bb);
    gemm_kernel<false><<<gav, 256>>>(s, NTOK, sNN, v, CC, sNC, ao, CC, sNC,
                                     nullptr, nullptr, 1.f, NTOK, CC, NTOK);

    // 6) output projection + bias + residual -> d_out
    gemm_kernel<false><<<gproj, 256>>>(ao, CC, 0, wo, CC, 0, out, CC, 0, bo, x, 1.f, Mtot, CC, CC);
}

// round 4
// speedup vs baseline: 1.0011x; 1.0011x over previous
#include <cuda_runtime.h>
#include <math.h>

#define Bb 8
#define HH 64
#define WWw 64
#define CC 512
#define GG 32
#define CGc (CC/GG)          /* 16 */
#define NTOK (HH*WWw)        /* 4096 */
#define EPSV 1e-5f

// ---------------- scratch (device globals; no runtime allocation) ----------------
__device__ float g_h [(size_t)Bb*NTOK*CC];
__device__ float g_q [(size_t)Bb*NTOK*CC];
__device__ float g_k [(size_t)Bb*NTOK*CC];
__device__ float g_v [(size_t)Bb*NTOK*CC];
__device__ float g_ao[(size_t)Bb*NTOK*CC];
__device__ float g_s [(size_t)Bb*NTOK*NTOK];   // 512 MB scores

// ---------------- GroupNorm ----------------
// one block per (batch, group); reduce over NTOK*CGc = 65536 elems
__global__ void gn_kernel(const float* __restrict__ x,
                          const float* __restrict__ sc,
                          const float* __restrict__ bi,
                          float* __restrict__ h) {
    int b = blockIdx.x / GG, g = blockIdx.x % GG;
    const float* xp = x + (size_t)b*NTOK*CC + g*CGc;
    float*       hp = h + (size_t)b*NTOK*CC + g*CGc;
    int tid = threadIdx.x;

    float s = 0.f, ss = 0.f;
    for (int i = tid; i < NTOK*CGc; i += 256) {
        int n = i >> 4, c = i & 15;
        float v = xp[(size_t)n*CC + c];
        s += v; ss += v*v;
    }
    __shared__ float r1[256], r2[256];
    r1[tid] = s; r2[tid] = ss; __syncthreads();
    for (int o = 128; o > 0; o >>= 1) {
        if (tid < o) { r1[tid] += r1[tid+o]; r2[tid] += r2[tid+o]; }
        __syncthreads();
    }
    const float invn = 1.f / (float)(NTOK*CGc);
    float mean = r1[0] * invn;
    float var  = r2[0] * invn - mean*mean;
    float inv  = rsqrtf(var + EPSV);

    for (int i = tid; i < NTOK*CGc; i += 256) {
        int n = i >> 4, c = i & 15;
        float v = xp[(size_t)n*CC + c];
        hp[(size_t)n*CC + c] = (v - mean) * inv * sc[g*CGc + c] + bi[g*CGc + c];
    }
}

// ---------------- tiled fp32 GEMM ----------------
// C[M,N] = alpha * A[M,K] @ op(B) + bias + resid
// TRANSB=false: B is [K,N] row-major.  TRANSB=true: B is [N,K] row-major (S = Q K^T).
#define BM 128
#define BN 128
#define BKK 16

template<bool TRANSB>
__global__ __launch_bounds__(256, 2)
void gemm_kernel(const float* __restrict__ A, int lda, long long sA,
                 const float* __restrict__ Bm, int ldb, long long sB,
                 float* __restrict__ Cm, int ldc, long long sC,
                 const float* __restrict__ bias,
                 const float* __restrict__ resid,
                 float alpha, int M, int Nc, int K) {
    __shared__ float As[BKK][BM+4];
    __shared__ float Bs[BKK][BN+4];

    const float* Ab = A  + (size_t)blockIdx.z * sA;
    const float* Bp = Bm + (size_t)blockIdx.z * sB;
    float*       Cb = Cm + (size_t)blockIdx.z * sC;
    const float* Rb = resid;   // only used when gridDim.z==1

    int m0 = blockIdx.y * BM, n0 = blockIdx.x * BN;
    int tid = threadIdx.x;
    int tx = tid & 15, ty = tid >> 4;

    float acc[8][8];
    #pragma unroll
    for (int i = 0; i < 8; i++)
        #pragma unroll
        for (int j = 0; j < 8; j++) acc[i][j] = 0.f;

    for (int k0 = 0; k0 < K; k0 += BKK) {
        // load A tile 128x16 (K contiguous per lane -> coalesced)
        #pragma unroll
        for (int t = 0; t < 2; t++) {
            int l  = tid + t*256;
            int m  = l >> 2;
            int kq = (l & 3) << 2;
            float4 v = *(const float4*)(Ab + (size_t)(m0+m)*lda + (k0+kq));
            As[kq+0][m] = v.x; As[kq+1][m] = v.y; As[kq+2][m] = v.z; As[kq+3][m] = v.w;
        }
        if (TRANSB) {
            #pragma unroll
            for (int t = 0; t < 2; t++) {
                int l  = tid + t*256;
                int n  = l >> 2;
                int kq = (l & 3) << 2;
                float4 v = *(const float4*)(Bp + (size_t)(n0+n)*ldb + (k0+kq));
                Bs[kq+0][n] = v.x; Bs[kq+1][n] = v.y; Bs[kq+2][n] = v.z; Bs[kq+3][n] = v.w;
            }
        } else {
            #pragma unroll
            for (int t = 0; t < 2; t++) {
                int l  = tid + t*256;
                int k  = l >> 5;
                int nq = (l & 31) << 2;
                *(float4*)&Bs[k][nq] = *(const float4*)(Bp + (size_t)(k0+k)*ldb + n0 + nq);
            }
        }
        __syncthreads();

        #pragma unroll
        for (int kk = 0; kk < BKK; kk++) {
            float a[8], b[8];
            *(float4*)&a[0] = *(const float4*)&As[kk][ty*4];
            *(float4*)&a[4] = *(const float4*)&As[kk][ty*4 + 64];
            *(float4*)&b[0] = *(const float4*)&Bs[kk][tx*4];
            *(float4*)&b[4] = *(const float4*)&Bs[kk][tx*4 + 64];
            #pragma unroll
            for (int i = 0; i < 8; i++)
                #pragma unroll
                for (int j = 0; j < 8; j++)
                    acc[i][j] = fmaf(a[i], b[j], acc[i][j]);
        }
        __syncthreads();
    }

    // epilogue: row(i) = m0 + ty*4 + (i%4) + (i/4)*64 ; col(j) analogous with tx
    #pragma unroll
    for (int i = 0; i < 8; i++) {
        int m = m0 + (ty<<2) + (i & 3) + ((i >> 2) << 6);
        size_t crow = (size_t)m * ldc;
        #pragma unroll
        for (int jh = 0; jh < 2; jh++) {
            int n = n0 + (tx<<2) + (jh << 6);
            float4 o;
            o.x = acc[i][jh*4+0] * alpha;
            o.y = acc[i][jh*4+1] * alpha;
            o.z = acc[i][jh*4+2] * alpha;
            o.w = acc[i][jh*4+3] * alpha;
            if (bias) {
                o.x += bias[n];   o.y += bias[n+1];
                o.z += bias[n+2]; o.w += bias[n+3];
            }
            if (Rb) {
                float4 r = *(const float4*)(Rb + crow + n);
                o.x += r.x; o.y += r.y; o.z += r.z; o.w += r.w;
            }
            *(float4*)(Cb + crow + n) = o;
        }
    }
}

// ---------------- row softmax (one block per row, values cached in regs) ----------------
__global__ void softmax_kernel(float* __restrict__ s) {
    size_t row = blockIdx.x;
    float* p = s + row * (size_t)NTOK;
    int tid = threadIdx.x;

    float vals[16];
    float m = -3.4e38f;
    #pragma unroll
    for (int t = 0; t < 16; t++) {
        vals[t] = p[tid + t*256];
        m = fmaxf(m, vals[t]);
    }
    __shared__ float red[256];
    red[tid] = m; __syncthreads();
    for (int o = 128; o > 0; o >>= 1) {
        if (tid < o) red[tid] = fmaxf(red[tid], red[tid+o]);
        __syncthreads();
    }
    m = red[0]; __syncthreads();

    float sum = 0.f;
    #pragma unroll
    for (int t = 0; t < 16; t++) {
        vals[t] = __expf(vals[t] - m);
        sum += vals[t];
    }
    red[tid] = sum; __syncthreads();
    for (int o = 128; o > 0; o >>= 1) {
        if (tid < o) red[tid] += red[tid+o];
        __syncthreads();
    }
    float r = 1.f / red[0];
    #pragma unroll
    for (int t = 0; t < 16; t++) p[tid + t*256] = vals[t] * r;
}

// ---------------- launch ----------------
extern "C" void kernel_launch(void* const* d_in, const int* in_sizes, int n_in,
                              void* d_out, int out_size) {
    const float* x  = (const float*)d_in[0];
    const float* gs = (const float*)d_in[1];
    const float* gb = (const float*)d_in[2];
    const float* wq = (const float*)d_in[3];
    const float* bq = (const float*)d_in[4];
    const float* wk = (const float*)d_in[5];
    const float* bk = (const float*)d_in[6];
    const float* wv = (const float*)d_in[7];
    const float* bv = (const float*)d_in[8];
    const float* wo = (const float*)d_in[9];
    const float* bo = (const float*)d_in[10];
    float* out = (float*)d_out;

    float *h, *q, *k, *v, *ao, *s;
    cudaGetSymbolAddress((void**)&h,  g_h);
    cudaGetSymbolAddress((void**)&q,  g_q);
    cudaGetSymbolAddress((void**)&k,  g_k);
    cudaGetSymbolAddress((void**)&v,  g_v);
    cudaGetSymbolAddress((void**)&ao, g_ao);
    cudaGetSymbolAddress((void**)&s,  g_s);

    const long long sNC = (long long)NTOK * CC;   // per-batch q/k/v stride
    const long long sNN = (long long)NTOK * NTOK; // per-batch scores stride
    const int Mtot = Bb * NTOK;                   // 32768
    const float inv_sqrt_c = 0.044194173824159216f; // 512^-0.5

    // 1) GroupNorm
    gn_kernel<<<Bb*GG, 256>>>(x, gs, gb, h);

    // 2) Q, K, V projections: [32768,512] @ [512,512] + bias
    dim3 gproj(CC/BN, Mtot/BM, 1);
    gemm_kernel<false><<<gproj, 256>>>(h, CC, 0, wq, CC, 0, q, CC, 0, bq, nullptr, 1.f, Mtot, CC, CC);
    gemm_kernel<false><<<gproj, 256>>>(h, CC, 0, wk, CC, 0, k, CC, 0, bk, nullptr, 1.f, Mtot, CC, CC);
    gemm_kernel<false><<<gproj, 256>>>(h, CC, 0, wv, CC, 0, v, CC, 0, bv, nullptr, 1.f, Mtot, CC, CC);

    // 3) scores = alpha * Q @ K^T  (batched over z)
    dim3 gsc(NTOK/BN, NTOK/BM, Bb);
    gemm_kernel<true><<<gsc, 256>>>(q, CC, sNC, k, CC, sNC, s, NTOK, sNN,
                                    nullptr, nullptr, inv_sqrt_c, NTOK, NTOK, CC);

    // 4) softmax over keys
    softmax_kernel<<<Bb*NTOK, 256>>>(s);

    // 5) attn @ V  (batched)
    dim3 gav(CC/BN, NTOK/BM, Bb);
    gemm_kernel<false><<<gav, 256>>>(s, NTOK, sNN, v, CC, sNC, ao, CC, sNC,
                                     nullptr, nullptr, 1.f, NTOK, CC, NTOK);

    // 6) output projection + bias + residual -> d_out
    gemm_kernel<false><<<gproj, 256>>>(ao, CC, 0, wo, CC, 0, out, CC, 0, bo, x, 1.f, Mtot, CC, CC);
}